// round 1
// baseline (speedup 1.0000x reference)
#include <cuda_runtime.h>
#include <math.h>

#define N 2048
#define NN (N*N)
#define K12 12
#define HID 64
#define H1 4
#define NT1 256
#define NG 8
#define OUTF 10

// ---------------- scratch (static device arrays; no allocation) ----------------
__device__ float g_edgeT[NN];          // 16 MB : edge_attr transposed [dst][src]
__device__ float g_mean[N];            // mean_e per dst
__device__ float g_we[H1];             // per-head edge weight scalar
__device__ float g_hf1[N*NT1];         // h1 features = x@W1
__device__ float g_as[N*H1];           // alpha_src per node/head
__device__ float g_ad[N*H1];           // alpha_dst per node/head
__device__ float g_P[H1*NN];           // 64 MB : unnormalized softmax P[h][dst][src]
__device__ float g_inv[N*H1];          // 1/softmax-sum per (dst,head)
__device__ float g_part[4*N*NT1];      // 8 MB split-K partials
__device__ float g_o1[N*NT1];          // elu(gat1)
__device__ float g_hf2[N*HID];
__device__ float g_o2[N*HID];

// ---------------- 1: agg = w.attn + b ; edge_attr = max(agg,0-masked) ----------------
__global__ void k_agg(const float* __restrict__ attn, const float* __restrict__ w,
                      const float* __restrict__ b, float* __restrict__ edge) {
    int idx = blockIdx.x * blockDim.x + threadIdx.x;   // float4 index
    if (idx >= NN / 4) return;
    float wv[K12];
#pragma unroll
    for (int k = 0; k < K12; k++) wv[k] = w[k];
    float bb = b[0];
    float4 acc = make_float4(bb, bb, bb, bb);
#pragma unroll
    for (int k = 0; k < K12; k++) {
        float4 v = *(const float4*)(attn + (size_t)k * NN + (size_t)idx * 4);
        acc.x += wv[k] * v.x; acc.y += wv[k] * v.y;
        acc.z += wv[k] * v.z; acc.w += wv[k] * v.w;
    }
    float4 e;
    e.x = acc.x > 0.f ? acc.x : 0.f;
    e.y = acc.y > 0.f ? acc.y : 0.f;
    e.z = acc.z > 0.f ? acc.z : 0.f;
    e.w = acc.w > 0.f ? acc.w : 0.f;
    *(float4*)(edge + (size_t)idx * 4) = e;
}

// ---------------- 2: transpose edge -> edgeT ----------------
__global__ void k_tr(const float* __restrict__ src, float* __restrict__ dst) {
    __shared__ float t[32][33];
    int bx = blockIdx.x * 32, by = blockIdx.y * 32;
    int tx = threadIdx.x;
    for (int yy = threadIdx.y; yy < 32; yy += 8)
        t[yy][tx] = src[(size_t)(by + yy) * N + bx + tx];
    __syncthreads();
    for (int yy = threadIdx.y; yy < 32; yy += 8)
        dst[(size_t)(bx + yy) * N + by + tx] = t[tx][yy];
}

// ---------------- 3: per-dst mean of masked edges (excl. diagonal) ----------------
__global__ void k_stats(const float* __restrict__ eT, float* __restrict__ mean) {
    int j = blockIdx.x;
    const float* row = eT + (size_t)j * N;
    float s = 0.f, c = 0.f;
    for (int i = threadIdx.x; i < N; i += 256) {
        float v = row[i];
        if (i != j && v > 0.f) { s += v; c += 1.f; }
    }
    __shared__ float ss[256], cs[256];
    ss[threadIdx.x] = s; cs[threadIdx.x] = c;
    __syncthreads();
    for (int st = 128; st > 0; st >>= 1) {
        if (threadIdx.x < st) { ss[threadIdx.x] += ss[threadIdx.x + st]; cs[threadIdx.x] += cs[threadIdx.x + st]; }
        __syncthreads();
    }
    if (threadIdx.x == 0) mean[j] = cs[0] > 0.f ? ss[0] / cs[0] : 0.f;
}

// ---------------- per-head edge-weight scalar ----------------
__global__ void k_we(const float* __restrict__ We, const float* __restrict__ ae,
                     float* __restrict__ we, int H) {
    int h = threadIdx.x;
    if (h < H) {
        float s = 0.f;
        for (int c = 0; c < HID; c++) s += We[h * HID + c] * ae[h * HID + c];
        we[h] = s;
    }
}

// ---------------- generic C = A@B (row-major), dims divisible by 64/16 ----------------
__global__ void k_gemm(const float* __restrict__ A, const float* __restrict__ B,
                       float* __restrict__ C, int M, int K, int Nn) {
    __shared__ float As[16][65];
    __shared__ float Bs[16][64];
    int m0 = blockIdx.x * 64, n0 = blockIdx.y * 64;
    int tid = threadIdx.x;
    int tx = tid & 15, ty = tid >> 4;
    float acc[4][4] = {};
    for (int k0 = 0; k0 < K; k0 += 16) {
#pragma unroll
        for (int l = 0; l < 4; l++) {
            int e = l * 256 + tid;
            As[e & 15][e >> 4] = A[(size_t)(m0 + (e >> 4)) * K + k0 + (e & 15)];
            Bs[e >> 6][e & 63] = B[(size_t)(k0 + (e >> 6)) * Nn + n0 + (e & 63)];
        }
        __syncthreads();
#pragma unroll
        for (int kk = 0; kk < 16; kk++) {
            float a[4], bb[4];
#pragma unroll
            for (int r = 0; r < 4; r++) a[r] = As[kk][ty * 4 + r];
#pragma unroll
            for (int c = 0; c < 4; c++) bb[c] = Bs[kk][tx * 4 + c];
#pragma unroll
            for (int r = 0; r < 4; r++)
#pragma unroll
                for (int c = 0; c < 4; c++) acc[r][c] += a[r] * bb[c];
        }
        __syncthreads();
    }
#pragma unroll
    for (int r = 0; r < 4; r++)
#pragma unroll
        for (int c = 0; c < 4; c++)
            C[(size_t)(m0 + ty * 4 + r) * Nn + n0 + tx * 4 + c] = acc[r][c];
}

// ---------------- attention source/dest dot products ----------------
__global__ void k_att(const float* __restrict__ hf, const float* __restrict__ asrc,
                      const float* __restrict__ adst, float* __restrict__ oas,
                      float* __restrict__ oad, int H) {
    int t = blockIdx.x * 256 + threadIdx.x;
    if (t >= N * H) return;
    int n = t / H, h = t % H;
    const float* row = hf + (size_t)n * (H * 64) + h * 64;
    float s = 0.f, d = 0.f;
    for (int c = 0; c < 64; c++) {
        float v = row[c];
        s += v * asrc[h * 64 + c];
        d += v * adst[h * 64 + c];
    }
    oas[t] = s; oad[t] = d;
}

// ---------------- logits + segment softmax -> unnormalized P, inverse sums ----------------
template<int H>
__global__ void k_logits(const float* __restrict__ eT, const float* __restrict__ mean,
                         const float* __restrict__ as_, const float* __restrict__ ad_,
                         const float* __restrict__ we_, float* __restrict__ P,
                         float* __restrict__ inv) {
    __shared__ float sl[H * N];
    __shared__ float red[H * 256];
    int j = blockIdx.x, tid = threadIdx.x;
    float adj[H], wev[H], lmax[H];
#pragma unroll
    for (int h = 0; h < H; h++) { adj[h] = ad_[j * H + h]; wev[h] = we_[h]; lmax[h] = -1e30f; }
    float me = mean[j];
    for (int i = tid; i < N; i += 256) {
        float ev = eT[(size_t)j * N + i];
        bool diag = (i == j);
        bool part = diag || (ev > 0.f);
        float e = diag ? me : ev;
#pragma unroll
        for (int h = 0; h < H; h++) {
            float v = as_[i * H + h] + adj[h] + e * wev[h];
            v = v > 0.f ? v : 0.2f * v;
            v = part ? v : -1e30f;
            sl[h * N + i] = v;
            lmax[h] = fmaxf(lmax[h], v);
        }
    }
#pragma unroll
    for (int h = 0; h < H; h++) red[h * 256 + tid] = lmax[h];
    __syncthreads();
    for (int s = 128; s > 0; s >>= 1) {
        if (tid < s)
#pragma unroll
            for (int h = 0; h < H; h++)
                red[h * 256 + tid] = fmaxf(red[h * 256 + tid], red[h * 256 + tid + s]);
        __syncthreads();
    }
    float gmax[H];
#pragma unroll
    for (int h = 0; h < H; h++) gmax[h] = red[h * 256];
    __syncthreads();
    float lsum[H];
#pragma unroll
    for (int h = 0; h < H; h++) lsum[h] = 0.f;
    for (int i = tid; i < N; i += 256) {
#pragma unroll
        for (int h = 0; h < H; h++) {
            float v = sl[h * N + i];
            float p = v > -1e29f ? expf(v - gmax[h]) : 0.f;
            P[(size_t)h * NN + (size_t)j * N + i] = p;
            lsum[h] += p;
        }
    }
#pragma unroll
    for (int h = 0; h < H; h++) red[h * 256 + tid] = lsum[h];
    __syncthreads();
    for (int s = 128; s > 0; s >>= 1) {
        if (tid < s)
#pragma unroll
            for (int h = 0; h < H; h++)
                red[h * 256 + tid] += red[h * 256 + tid + s];
        __syncthreads();
    }
    if (tid < H) inv[j * H + tid] = 1.f / red[tid * 256];
}

// ---------------- split-K aggregation GEMM: part[kz] += P[h][dst][src] * Hf[src][h*64+c] ----------------
__global__ void k_agemm(const float* __restrict__ P, const float* __restrict__ Hf,
                        float* __restrict__ part, int Ntot, int Kseg) {
    __shared__ float As[16][129];
    __shared__ float Bs[16][64];
    int h = blockIdx.x;
    int m0 = blockIdx.y * 128;
    int kz = blockIdx.z;
    const float* A = P + (size_t)h * NN;
    int tid = threadIdx.x;
    int tx = tid & 15, ty = tid >> 4;
    float acc[8][4] = {};
    int kb = kz * Kseg;
    for (int k0 = kb; k0 < kb + Kseg; k0 += 16) {
#pragma unroll
        for (int l = 0; l < 8; l++) {
            int e = l * 256 + tid;
            As[e & 15][e >> 4] = A[(size_t)(m0 + (e >> 4)) * N + k0 + (e & 15)];
        }
#pragma unroll
        for (int l = 0; l < 4; l++) {
            int e = l * 256 + tid;
            Bs[e >> 6][e & 63] = Hf[(size_t)(k0 + (e >> 6)) * Ntot + h * 64 + (e & 63)];
        }
        __syncthreads();
#pragma unroll
        for (int kk = 0; kk < 16; kk++) {
            float bb[4];
#pragma unroll
            for (int c = 0; c < 4; c++) bb[c] = Bs[kk][tx * 4 + c];
#pragma unroll
            for (int r = 0; r < 8; r++) {
                float a = As[kk][ty * 8 + r];
#pragma unroll
                for (int c = 0; c < 4; c++) acc[r][c] += a * bb[c];
            }
        }
        __syncthreads();
    }
#pragma unroll
    for (int r = 0; r < 8; r++)
#pragma unroll
        for (int c = 0; c < 4; c++)
            part[((size_t)kz * N + m0 + ty * 8 + r) * Ntot + h * 64 + tx * 4 + c] = acc[r][c];
}

// ---------------- epilogue: reduce split-K, normalize, +bias, elu ----------------
__global__ void k_epi(const float* __restrict__ part, const float* __restrict__ inv,
                      const float* __restrict__ bias, float* __restrict__ outp,
                      int Ntot, int H, int KS) {
    int idx = blockIdx.x * 256 + threadIdx.x;
    int total = N * Ntot;
    if (idx >= total) return;
    int m = idx / Ntot, c = idx % Ntot;
    float s = 0.f;
    for (int z = 0; z < KS; z++) s += part[(size_t)z * total + idx];
    float v = inv[m * H + c / 64] * s + bias[c];
    outp[idx] = v > 0.f ? v : (expf(v) - 1.f);
}

// ---------------- segment-mean pool + final linear ----------------
__global__ void k_pool(const float* __restrict__ o2, const int* __restrict__ batch,
                       const float* __restrict__ Wl, const float* __restrict__ bl,
                       float* __restrict__ out) {
    int g = blockIdx.x;
    __shared__ float acc[4][64];
    __shared__ float cnts[4];
    int tid = threadIdx.x, q = tid >> 6, c = tid & 63;
    float s = 0.f, cn = 0.f;
    for (int n = q; n < N; n += 4) {
        if (batch[n] == g) { s += o2[(size_t)n * 64 + c]; cn += 1.f; }
    }
    acc[q][c] = s;
    if (c == 0) cnts[q] = cn;
    __syncthreads();
    if (q == 0) {
        float tot = acc[0][c] + acc[1][c] + acc[2][c] + acc[3][c];
        float cc = cnts[0] + cnts[1] + cnts[2] + cnts[3];
        acc[0][c] = tot / fmaxf(cc, 1.f);
    }
    __syncthreads();
    if (tid < OUTF) {
        float s2 = bl[tid];
        for (int c2 = 0; c2 < 64; c2++) s2 += acc[0][c2] * Wl[c2 * OUTF + tid];
        out[g * OUTF + tid] = s2;
    }
}

// ---------------- host ----------------
extern "C" void kernel_launch(void* const* d_in, const int* in_sizes, int n_in,
                              void* d_out, int out_size) {
    const float* x        = (const float*)d_in[0];
    const float* attn     = (const float*)d_in[1];
    const int*   batch    = (const int*)d_in[2];
    const float* w_agg    = (const float*)d_in[3];
    const float* b_agg    = (const float*)d_in[4];
    const float* W1       = (const float*)d_in[5];
    const float* att_src1 = (const float*)d_in[6];
    const float* att_dst1 = (const float*)d_in[7];
    const float* We1      = (const float*)d_in[8];
    const float* att_e1   = (const float*)d_in[9];
    const float* bias1    = (const float*)d_in[10];
    const float* W2       = (const float*)d_in[11];
    const float* att_src2 = (const float*)d_in[12];
    const float* att_dst2 = (const float*)d_in[13];
    const float* We2      = (const float*)d_in[14];
    const float* att_e2   = (const float*)d_in[15];
    const float* bias2    = (const float*)d_in[16];
    const float* W_lin    = (const float*)d_in[17];
    const float* b_lin    = (const float*)d_in[18];

    float* out  = (float*)d_out;
    float* edge = out + (out_size - NN);   // edge_attr occupies the tail of d_out

    float *edgeT, *meanp, *wep, *hf1, *asp, *adp, *Pp, *invp, *partp, *o1p, *hf2p, *o2p;
    cudaGetSymbolAddress((void**)&edgeT, g_edgeT);
    cudaGetSymbolAddress((void**)&meanp, g_mean);
    cudaGetSymbolAddress((void**)&wep,   g_we);
    cudaGetSymbolAddress((void**)&hf1,   g_hf1);
    cudaGetSymbolAddress((void**)&asp,   g_as);
    cudaGetSymbolAddress((void**)&adp,   g_ad);
    cudaGetSymbolAddress((void**)&Pp,    g_P);
    cudaGetSymbolAddress((void**)&invp,  g_inv);
    cudaGetSymbolAddress((void**)&partp, g_part);
    cudaGetSymbolAddress((void**)&o1p,   g_o1);
    cudaGetSymbolAddress((void**)&hf2p,  g_hf2);
    cudaGetSymbolAddress((void**)&o2p,   g_o2);

    // 1) edge_attr (also part of the output)
    k_agg<<<NN / 4 / 256, 256>>>(attn, w_agg, b_agg, edge);
    // 2) transpose + per-dst stats
    k_tr<<<dim3(N / 32, N / 32), dim3(32, 8)>>>(edge, edgeT);
    k_stats<<<N, 256>>>(edgeT, meanp);

    // ---- GAT layer 1 (H=4, C=64) ----
    k_we<<<1, 32>>>(We1, att_e1, wep, H1);
    k_gemm<<<dim3(N / 64, NT1 / 64), 256>>>(x, W1, hf1, N, 128, NT1);
    k_att<<<(N * H1 + 255) / 256, 256>>>(hf1, att_src1, att_dst1, asp, adp, H1);
    k_logits<H1><<<N, 256>>>(edgeT, meanp, asp, adp, wep, Pp, invp);
    k_agemm<<<dim3(H1, N / 128, 4), 256>>>(Pp, hf1, partp, NT1, N / 4);
    k_epi<<<(N * NT1 + 255) / 256, 256>>>(partp, invp, bias1, o1p, NT1, H1, 4);

    // ---- GAT layer 2 (H=1, C=64) ----
    k_we<<<1, 32>>>(We2, att_e2, wep, 1);
    k_gemm<<<dim3(N / 64, HID / 64), 256>>>(o1p, W2, hf2p, N, NT1, HID);
    k_att<<<(N + 255) / 256, 256>>>(hf2p, att_src2, att_dst2, asp, adp, 1);
    k_logits<1><<<N, 256>>>(edgeT, meanp, asp, adp, wep, Pp, invp);
    k_agemm<<<dim3(1, N / 128, 8), 256>>>(Pp, hf2p, partp, HID, N / 8);
    k_epi<<<(N * HID + 255) / 256, 256>>>(partp, invp, bias2, o2p, HID, 1, 8);

    // ---- pool + final linear ----
    k_pool<<<NG, 256>>>(o2p, batch, W_lin, b_lin, out);
}

// round 4
// speedup vs baseline: 1.1635x; 1.1635x over previous
#include <cuda_runtime.h>
#include <cuda_bf16.h>
#include <cstdint>
#include <math.h>

#define N 2048
#define NN (N*N)
#define K12 12
#define HID 64
#define H1 4
#define NT1 256
#define NG 8
#define OUTF 10

// ---------------- scratch (static device arrays; no allocation) ----------------
__device__ float g_edgeT[NN];                 // 16 MB : edge transposed [dst][src]
__device__ float g_mean[N];
__device__ float g_hf1[N*NT1];                // x@W1 fp32
__device__ float g_hf1t[N*NT1];               // tf32-rounded copy for MMA
__device__ float g_hf2[N*HID];
__device__ float g_hf2t[N*HID];
__device__ float g_as[N*H1];
__device__ float g_ad[N*H1];
__device__ float g_inv[N*H1];
__device__ float g_P[(size_t)H1*NN];          // 64 MB : unnormalized softmax (tf32-rounded)
__device__ float g_part[4*N*HID];             // split-K partials (layer 2)
__device__ float g_o1[N*NT1];
__device__ float g_o2[N*HID];

__device__ __forceinline__ float to_tf32(float x) {
    unsigned int u;
    asm("cvt.rna.tf32.f32 %0, %1;" : "=r"(u) : "f"(x));
    return __uint_as_float(u);
}

// ---------------- 1: agg = w.attn + b ; edge = relu ; edgeT (fused transpose) ----------------
__global__ void __launch_bounds__(256) k_aggT(const float* __restrict__ attn,
                                              const float* __restrict__ w,
                                              const float* __restrict__ b,
                                              float* __restrict__ edge,
                                              float* __restrict__ edgeT) {
    __shared__ float t[64][65];
    int bx = blockIdx.x * 64, by = blockIdx.y * 64;
    int tid = threadIdx.x;
    int tx = tid & 15, ty = tid >> 4;
    float wv[K12];
#pragma unroll
    for (int k = 0; k < K12; k++) wv[k] = w[k];
    float bb = b[0];
#pragma unroll
    for (int rr = 0; rr < 4; rr++) {
        int row = rr * 16 + ty;
        float4 acc = make_float4(bb, bb, bb, bb);
#pragma unroll
        for (int k = 0; k < K12; k++) {
            float4 v = *(const float4*)(attn + (size_t)k * NN + (size_t)(by + row) * N + bx + tx * 4);
            acc.x += wv[k] * v.x; acc.y += wv[k] * v.y;
            acc.z += wv[k] * v.z; acc.w += wv[k] * v.w;
        }
        acc.x = acc.x > 0.f ? acc.x : 0.f;
        acc.y = acc.y > 0.f ? acc.y : 0.f;
        acc.z = acc.z > 0.f ? acc.z : 0.f;
        acc.w = acc.w > 0.f ? acc.w : 0.f;
        *(float4*)(edge + (size_t)(by + row) * N + bx + tx * 4) = acc;
        t[row][tx * 4 + 0] = acc.x; t[row][tx * 4 + 1] = acc.y;
        t[row][tx * 4 + 2] = acc.z; t[row][tx * 4 + 3] = acc.w;
    }
    __syncthreads();
#pragma unroll
    for (int rr = 0; rr < 4; rr++) {
        int jj = rr * 16 + ty;
        float4 o;
        o.x = t[tx * 4 + 0][jj]; o.y = t[tx * 4 + 1][jj];
        o.z = t[tx * 4 + 2][jj]; o.w = t[tx * 4 + 3][jj];
        *(float4*)(edgeT + (size_t)(bx + jj) * N + by + tx * 4) = o;
    }
}

// ---------------- 2: per-dst mean of masked edges (excl. diagonal) ----------------
__global__ void k_stats(const float* __restrict__ eT, float* __restrict__ mean) {
    int j = blockIdx.x;
    const float* row = eT + (size_t)j * N;
    float s = 0.f, c = 0.f;
    for (int i = threadIdx.x; i < N; i += 256) {
        float v = row[i];
        if (i != j && v > 0.f) { s += v; c += 1.f; }
    }
    __shared__ float ss[256], cs[256];
    ss[threadIdx.x] = s; cs[threadIdx.x] = c;
    __syncthreads();
    for (int st = 128; st > 0; st >>= 1) {
        if (threadIdx.x < st) { ss[threadIdx.x] += ss[threadIdx.x + st]; cs[threadIdx.x] += cs[threadIdx.x + st]; }
        __syncthreads();
    }
    if (threadIdx.x == 0) mean[j] = cs[0] > 0.f ? ss[0] / cs[0] : 0.f;
}

// ---------------- generic C = A@B fp32 SIMT (feature GEMMs, small) ----------------
__global__ void k_gemm(const float* __restrict__ A, const float* __restrict__ B,
                       float* __restrict__ C, int M, int K, int Nn) {
    __shared__ float As[16][65];
    __shared__ float Bs[16][64];
    int m0 = blockIdx.x * 64, n0 = blockIdx.y * 64;
    int tid = threadIdx.x;
    int tx = tid & 15, ty = tid >> 4;
    float acc[4][4] = {};
    for (int k0 = 0; k0 < K; k0 += 16) {
#pragma unroll
        for (int l = 0; l < 4; l++) {
            int e = l * 256 + tid;
            As[e & 15][e >> 4] = A[(size_t)(m0 + (e >> 4)) * K + k0 + (e & 15)];
            Bs[e >> 6][e & 63] = B[(size_t)(k0 + (e >> 6)) * Nn + n0 + (e & 63)];
        }
        __syncthreads();
#pragma unroll
        for (int kk = 0; kk < 16; kk++) {
            float a[4], bb[4];
#pragma unroll
            for (int r = 0; r < 4; r++) a[r] = As[kk][ty * 4 + r];
#pragma unroll
            for (int c = 0; c < 4; c++) bb[c] = Bs[kk][tx * 4 + c];
#pragma unroll
            for (int r = 0; r < 4; r++)
#pragma unroll
                for (int c = 0; c < 4; c++) acc[r][c] += a[r] * bb[c];
        }
        __syncthreads();
    }
#pragma unroll
    for (int r = 0; r < 4; r++)
#pragma unroll
        for (int c = 0; c < 4; c++)
            C[(size_t)(m0 + ty * 4 + r) * Nn + n0 + tx * 4 + c] = acc[r][c];
}

// ---------------- attention dots + tf32-rounded feature copy ----------------
template<int H>
__global__ void k_att(const float* __restrict__ hf, const float* __restrict__ asrc,
                      const float* __restrict__ adst, float* __restrict__ oas,
                      float* __restrict__ oad, float* __restrict__ hft) {
    const int NC = H * 64;
    __shared__ float row[256];
    int n = blockIdx.x, tid = threadIdx.x;
    if (tid < NC) {
        float v = hf[(size_t)n * NC + tid];
        row[tid] = v;
        hft[(size_t)n * NC + tid] = to_tf32(v);
    }
    __syncthreads();
    int w = tid >> 5, lane = tid & 31;
    int h = w & 3;
    if (h < H) {
        const float* att = (w < 4) ? asrc : adst;
        float s = row[h * 64 + lane] * att[h * 64 + lane]
                + row[h * 64 + 32 + lane] * att[h * 64 + 32 + lane];
        for (int o = 16; o; o >>= 1) s += __shfl_xor_sync(0xffffffffu, s, o);
        if (lane == 0) { if (w < 4) oas[n * H + h] = s; else oad[n * H + h] = s; }
    }
}

// ---------------- logits + max-free segment softmax -> tf32 P + inverse sums ----------------
template<int H>
__global__ void __launch_bounds__(256) k_logits(const float* __restrict__ eT,
        const float* __restrict__ mean, const float* __restrict__ as_,
        const float* __restrict__ ad_, const float* __restrict__ We,
        const float* __restrict__ ae, float* __restrict__ P,
        float* __restrict__ inv) {
    const int JB = 4;
    __shared__ float s_as[N * H];
    __shared__ float s_we[H];
    __shared__ float s_adj[JB * H];
    __shared__ float s_me[JB];
    __shared__ float red[8][JB * H];
    int tid = threadIdx.x;
    int j0 = blockIdx.x * JB;
    for (int idx = tid; idx < N * H; idx += 256) s_as[idx] = as_[idx];
    if (tid < H) {
        float s = 0.f;
        for (int c = 0; c < 64; c++) s += We[tid * 64 + c] * ae[tid * 64 + c];
        s_we[tid] = s;
    }
    if (tid < JB * H) s_adj[tid] = ad_[(j0 + tid / H) * H + (tid % H)];
    if (tid < JB) s_me[tid] = mean[j0 + tid];
    __syncthreads();
    float lsum[JB][H];
#pragma unroll
    for (int jj = 0; jj < JB; jj++)
#pragma unroll
        for (int h = 0; h < H; h++) lsum[jj][h] = 0.f;
    for (int i = tid; i < N; i += 256) {
        float asv[H];
        if (H == 4) {
            float4 a4 = ((const float4*)s_as)[i];
            asv[0] = a4.x; if (H > 1) { asv[1] = a4.y; asv[2] = a4.z; asv[3] = a4.w; }
        } else {
            asv[0] = s_as[i];
        }
#pragma unroll
        for (int jj = 0; jj < JB; jj++) {
            float ev = eT[(size_t)(j0 + jj) * N + i];
            bool diag = (i == j0 + jj);
            float e = diag ? s_me[jj] : ev;
            bool part = diag || (ev > 0.f);
#pragma unroll
            for (int h = 0; h < H; h++) {
                float v = asv[h] + s_adj[jj * H + h] + e * s_we[h];
                v = v > 0.f ? v : 0.2f * v;
                float p = part ? to_tf32(__expf(v)) : 0.f;
                P[(size_t)h * NN + (size_t)(j0 + jj) * N + i] = p;
                lsum[jj][h] += p;
            }
        }
    }
#pragma unroll
    for (int jj = 0; jj < JB; jj++)
#pragma unroll
        for (int h = 0; h < H; h++)
            for (int o = 16; o; o >>= 1)
                lsum[jj][h] += __shfl_xor_sync(0xffffffffu, lsum[jj][h], o);
    int w = tid >> 5, lane = tid & 31;
    if (lane == 0)
#pragma unroll
        for (int jj = 0; jj < JB; jj++)
#pragma unroll
            for (int h = 0; h < H; h++) red[w][jj * H + h] = lsum[jj][h];
    __syncthreads();
    if (tid < JB * H) {
        float s = 0.f;
        for (int ww = 0; ww < 8; ww++) s += red[ww][tid];
        inv[(j0 + tid / H) * H + (tid % H)] = 1.f / s;
    }
}

// ---------------- tf32 tensor-core aggregation GEMM: C = P_h @ Hf_h ----------------
template<bool EPI>
__global__ void __launch_bounds__(256) k_mma(const float* __restrict__ P,
        const float* __restrict__ Bf, float* __restrict__ out,
        const float* __restrict__ inv, const float* __restrict__ bias,
        int ldb, int H, int Kseg) {
    __shared__ float As[64][36];   // pad 4 : frag banks (row>>0)*36+(k&7) conflict-free
    __shared__ float Bs[32][68];   // pad 4 : frag banks 4k+col conflict-free
    int m0 = blockIdx.x * 64;
    int h = blockIdx.y;
    int kb = blockIdx.z * Kseg;
    const float* A = P + (size_t)h * NN;
    int tid = threadIdx.x;
    int wid = tid >> 5, lane = tid & 31;
    int wm = wid >> 2, wn = wid & 3;       // warp tile: m32 x n16
    int gid = lane >> 2, tig = lane & 3;
    int arow = tid >> 2, ac4 = tid & 3;    // A: 64 rows, 4 thr/row, 2 float4 each
    int brow = tid >> 3, bc8 = tid & 7;    // B: 32 rows, 8 thr/row, 2 float4 each

    float acc[2][2][4];
#pragma unroll
    for (int mt = 0; mt < 2; mt++)
#pragma unroll
        for (int nt = 0; nt < 2; nt++)
#pragma unroll
            for (int q = 0; q < 4; q++) acc[mt][nt][q] = 0.f;

    float4 av0 = *(const float4*)(A + (size_t)(m0 + arow) * N + kb + ac4 * 8);
    float4 av1 = *(const float4*)(A + (size_t)(m0 + arow) * N + kb + ac4 * 8 + 4);
    float4 bv0 = *(const float4*)(Bf + (size_t)(kb + brow) * ldb + h * 64 + bc8 * 8);
    float4 bv1 = *(const float4*)(Bf + (size_t)(kb + brow) * ldb + h * 64 + bc8 * 8 + 4);

    for (int k0 = kb; k0 < kb + Kseg; k0 += 32) {
        *(float4*)&As[arow][ac4 * 8]     = av0;
        *(float4*)&As[arow][ac4 * 8 + 4] = av1;
        *(float4*)&Bs[brow][bc8 * 8]     = bv0;
        *(float4*)&Bs[brow][bc8 * 8 + 4] = bv1;
        __syncthreads();
        if (k0 + 32 < kb + Kseg) {
            av0 = *(const float4*)(A + (size_t)(m0 + arow) * N + k0 + 32 + ac4 * 8);
            av1 = *(const float4*)(A + (size_t)(m0 + arow) * N + k0 + 32 + ac4 * 8 + 4);
            bv0 = *(const float4*)(Bf + (size_t)(k0 + 32 + brow) * ldb + h * 64 + bc8 * 8);
            bv1 = *(const float4*)(Bf + (size_t)(k0 + 32 + brow) * ldb + h * 64 + bc8 * 8 + 4);
        }
#pragma unroll
        for (int kk = 0; kk < 4; kk++) {   // four k8 steps
            float a[2][4], bq[2][2];
#pragma unroll
            for (int mt = 0; mt < 2; mt++) {
                int r0 = wm * 32 + mt * 16 + gid;
                a[mt][0] = As[r0][kk * 8 + tig];
                a[mt][1] = As[r0 + 8][kk * 8 + tig];
                a[mt][2] = As[r0][kk * 8 + tig + 4];
                a[mt][3] = As[r0 + 8][kk * 8 + tig + 4];
            }
#pragma unroll
            for (int nt = 0; nt < 2; nt++) {
                int c0 = wn * 16 + nt * 8 + gid;
                bq[nt][0] = Bs[kk * 8 + tig][c0];
                bq[nt][1] = Bs[kk * 8 + tig + 4][c0];
            }
#pragma unroll
            for (int mt = 0; mt < 2; mt++)
#pragma unroll
                for (int nt = 0; nt < 2; nt++)
                    asm volatile("mma.sync.aligned.m16n8k8.row.col.f32.tf32.tf32.f32 "
                                 "{%0,%1,%2,%3}, {%4,%5,%6,%7}, {%8,%9}, {%0,%1,%2,%3};"
                                 : "+f"(acc[mt][nt][0]), "+f"(acc[mt][nt][1]),
                                   "+f"(acc[mt][nt][2]), "+f"(acc[mt][nt][3])
                                 : "r"(__float_as_uint(a[mt][0])), "r"(__float_as_uint(a[mt][1])),
                                   "r"(__float_as_uint(a[mt][2])), "r"(__float_as_uint(a[mt][3])),
                                   "r"(__float_as_uint(bq[nt][0])), "r"(__float_as_uint(bq[nt][1])));
        }
        __syncthreads();
    }

#pragma unroll
    for (int mt = 0; mt < 2; mt++) {
#pragma unroll
        for (int nt = 0; nt < 2; nt++) {
            int c0 = wn * 16 + nt * 8 + tig * 2;
#pragma unroll
            for (int pr = 0; pr < 2; pr++) {
                int r = m0 + wm * 32 + mt * 16 + gid + pr * 8;
                float v0 = acc[mt][nt][2 * pr + 0];
                float v1 = acc[mt][nt][2 * pr + 1];
                if (EPI) {
                    float vi = inv[r * H + h];
                    float a0 = v0 * vi + bias[h * 64 + c0];
                    float a1 = v1 * vi + bias[h * 64 + c0 + 1];
                    a0 = a0 > 0.f ? a0 : (expf(a0) - 1.f);
                    a1 = a1 > 0.f ? a1 : (expf(a1) - 1.f);
                    out[(size_t)r * (H * 64) + h * 64 + c0]     = a0;
                    out[(size_t)r * (H * 64) + h * 64 + c0 + 1] = a1;
                } else {
                    out[((size_t)blockIdx.z * N + r) * 64 + c0]     = v0;
                    out[((size_t)blockIdx.z * N + r) * 64 + c0 + 1] = v1;
                }
            }
        }
    }
}

// ---------------- layer-2 epilogue: combine split-K, normalize, bias, elu ----------------
__global__ void k_epi2(const float* __restrict__ part, const float* __restrict__ inv,
                       const float* __restrict__ bias, float* __restrict__ o2) {
    int idx = blockIdx.x * 256 + threadIdx.x;
    if (idx >= N * HID) return;
    int m = idx >> 6, c = idx & 63;
    float s = part[idx] + part[N * HID + idx] + part[2 * N * HID + idx] + part[3 * N * HID + idx];
    float v = inv[m] * s + bias[c];
    o2[idx] = v > 0.f ? v : (expf(v) - 1.f);
}

// ---------------- segment-mean pool + final linear ----------------
__global__ void k_pool(const float* __restrict__ o2, const int* __restrict__ batch,
                       const float* __restrict__ Wl, const float* __restrict__ bl,
                       float* __restrict__ out) {
    int g = blockIdx.x;
    __shared__ float acc[4][64];
    __shared__ float cnts[4];
    int tid = threadIdx.x, q = tid >> 6, c = tid & 63;
    float s = 0.f, cn = 0.f;
    for (int n = q; n < N; n += 4) {
        if (batch[n] == g) { s += o2[(size_t)n * 64 + c]; cn += 1.f; }
    }
    acc[q][c] = s;
    if (c == 0) cnts[q] = cn;
    __syncthreads();
    if (q == 0) {
        float tot = acc[0][c] + acc[1][c] + acc[2][c] + acc[3][c];
        float cc = cnts[0] + cnts[1] + cnts[2] + cnts[3];
        acc[0][c] = tot / fmaxf(cc, 1.f);
    }
    __syncthreads();
    if (tid < OUTF) {
        float s2 = bl[tid];
        for (int c2 = 0; c2 < 64; c2++) s2 += acc[0][c2] * Wl[c2 * OUTF + tid];
        out[g * OUTF + tid] = s2;
    }
}

// ---------------- host ----------------
extern "C" void kernel_launch(void* const* d_in, const int* in_sizes, int n_in,
                              void* d_out, int out_size) {
    const float* x        = (const float*)d_in[0];
    const float* attn     = (const float*)d_in[1];
    const int*   batch    = (const int*)d_in[2];
    const float* w_agg    = (const float*)d_in[3];
    const float* b_agg    = (const float*)d_in[4];
    const float* W1       = (const float*)d_in[5];
    const float* att_src1 = (const float*)d_in[6];
    const float* att_dst1 = (const float*)d_in[7];
    const float* We1      = (const float*)d_in[8];
    const float* att_e1   = (const float*)d_in[9];
    const float* bias1    = (const float*)d_in[10];
    const float* W2       = (const float*)d_in[11];
    const float* att_src2 = (const float*)d_in[12];
    const float* att_dst2 = (const float*)d_in[13];
    const float* We2      = (const float*)d_in[14];
    const float* att_e2   = (const float*)d_in[15];
    const float* bias2    = (const float*)d_in[16];
    const float* W_lin    = (const float*)d_in[17];
    const float* b_lin    = (const float*)d_in[18];

    float* out  = (float*)d_out;
    float* edge = out + (out_size - NN);

    float *edgeT, *meanp, *hf1, *hf1t, *hf2, *hf2t, *asp, *adp, *invp, *Pp, *partp, *o1p, *o2p;
    cudaGetSymbolAddress((void**)&edgeT, g_edgeT);
    cudaGetSymbolAddress((void**)&meanp, g_mean);
    cudaGetSymbolAddress((void**)&hf1,   g_hf1);
    cudaGetSymbolAddress((void**)&hf1t,  g_hf1t);
    cudaGetSymbolAddress((void**)&hf2,   g_hf2);
    cudaGetSymbolAddress((void**)&hf2t,  g_hf2t);
    cudaGetSymbolAddress((void**)&asp,   g_as);
    cudaGetSymbolAddress((void**)&adp,   g_ad);
    cudaGetSymbolAddress((void**)&invp,  g_inv);
    cudaGetSymbolAddress((void**)&Pp,    g_P);
    cudaGetSymbolAddress((void**)&partp, g_part);
    cudaGetSymbolAddress((void**)&o1p,   g_o1);
    cudaGetSymbolAddress((void**)&o2p,   g_o2);

    // edge + edgeT (fused), stats
    k_aggT<<<dim3(32, 32), 256>>>(attn, w_agg, b_agg, edge, edgeT);
    k_stats<<<N, 256>>>(edgeT, meanp);

    // ---- GAT layer 1 (H=4, C=64) ----
    k_gemm<<<dim3(32, 4), 256>>>(x, W1, hf1, N, 128, NT1);
    k_att<H1><<<N, 256>>>(hf1, att_src1, att_dst1, asp, adp, hf1t);
    k_logits<H1><<<N / 4, 256>>>(edgeT, meanp, asp, adp, We1, att_e1, Pp, invp);
    k_mma<true><<<dim3(32, 4, 1), 256>>>(Pp, hf1t, o1p, invp, bias1, NT1, H1, N);

    // ---- GAT layer 2 (H=1, C=64) ----
    k_gemm<<<dim3(32, 1), 256>>>(o1p, W2, hf2, N, NT1, HID);
    k_att<1><<<N, 256>>>(hf2, att_src2, att_dst2, asp, adp, hf2t);
    k_logits<1><<<N / 4, 256>>>(edgeT, meanp, asp, adp, We2, att_e2, Pp, invp);
    k_mma<false><<<dim3(32, 1, 4), 256>>>(Pp, hf2t, partp, nullptr, nullptr, HID, 1, N / 4);
    k_epi2<<<(N * HID + 255) / 256, 256>>>(partp, invp, bias2, o2p);

    // ---- pool + final linear ----
    k_pool<<<NG, 256>>>(o2p, batch, W_lin, b_lin, out);
}

// round 5
// speedup vs baseline: 1.3155x; 1.1307x over previous
#include <cuda_runtime.h>
#include <cuda_bf16.h>
#include <cstdint>
#include <math.h>

#define N 2048
#define NN (N*N)
#define K12 12
#define H1 4
#define NG 8
#define OUTF 10
#define KCH 32

// ---------------- scratch ----------------
__device__ float g_csum[32*N];
__device__ float g_ccnt[32*N];
__device__ float g_mean[N];
__device__ float g_we[8];
__device__ float g_hf1t[N*256];     // tf32-rounded features layer1
__device__ float g_hf2t[N*64];
__device__ float g_as[H1*N];        // [h][n]
__device__ float g_ad[H1*N];
__device__ float g_part[2*N*256];   // split partial C (1M floats, shared both layers)
__device__ float g_rsum[8*N];       // split partial row-sums
__device__ float g_o1[N*256];
__device__ float g_o2[N*64];

__device__ __forceinline__ float to_tf32(float x) {
    unsigned int u;
    asm("cvt.rna.tf32.f32 %0, %1;" : "=r"(u) : "f"(x));
    return __uint_as_float(u);
}

// ---------------- 1: agg = w.attn + b ; edge = relu ; per-tile column stats ----------------
__global__ void __launch_bounds__(256) k_aggT(const float* __restrict__ attn,
                                              const float* __restrict__ w,
                                              const float* __restrict__ b,
                                              float* __restrict__ edge,
                                              float* __restrict__ csum,
                                              float* __restrict__ ccnt) {
    __shared__ float t[64][65];
    __shared__ float cr[4][64], cc2[4][64];
    int bx = blockIdx.x * 64, by = blockIdx.y * 64;
    int tid = threadIdx.x;
    int tx = tid & 15, ty = tid >> 4;
    float wv[K12];
#pragma unroll
    for (int k = 0; k < K12; k++) wv[k] = w[k];
    float bb = b[0];
#pragma unroll
    for (int rr = 0; rr < 4; rr++) {
        int row = rr * 16 + ty;
        float4 acc = make_float4(bb, bb, bb, bb);
#pragma unroll
        for (int k = 0; k < K12; k++) {
            float4 v = *(const float4*)(attn + (size_t)k * NN + (size_t)(by + row) * N + bx + tx * 4);
            acc.x += wv[k] * v.x; acc.y += wv[k] * v.y;
            acc.z += wv[k] * v.z; acc.w += wv[k] * v.w;
        }
        acc.x = acc.x > 0.f ? acc.x : 0.f;
        acc.y = acc.y > 0.f ? acc.y : 0.f;
        acc.z = acc.z > 0.f ? acc.z : 0.f;
        acc.w = acc.w > 0.f ? acc.w : 0.f;
        *(float4*)(edge + (size_t)(by + row) * N + bx + tx * 4) = acc;
        t[row][tx * 4 + 0] = acc.x; t[row][tx * 4 + 1] = acc.y;
        t[row][tx * 4 + 2] = acc.z; t[row][tx * 4 + 3] = acc.w;
    }
    __syncthreads();
    // column stats (dst = column), excluding diagonal
    int col = tid & 63, g = tid >> 6;
    float s = 0.f, cn = 0.f;
#pragma unroll
    for (int rr = 0; rr < 16; rr++) {
        int row = g * 16 + rr;
        float v = t[row][col];
        if (v > 0.f && (by + row != bx + col)) { s += v; cn += 1.f; }
    }
    cr[g][col] = s; cc2[g][col] = cn;
    __syncthreads();
    if (tid < 64) {
        csum[blockIdx.y * N + bx + tid] = cr[0][tid] + cr[1][tid] + cr[2][tid] + cr[3][tid];
        ccnt[blockIdx.y * N + bx + tid] = cc2[0][tid] + cc2[1][tid] + cc2[2][tid] + cc2[3][tid];
    }
}

// ---------------- 2: means + per-head edge weights ----------------
__global__ void k_mean(const float* __restrict__ cs, const float* __restrict__ cc,
                       float* __restrict__ mean,
                       const float* __restrict__ We1, const float* __restrict__ ae1,
                       const float* __restrict__ We2, const float* __restrict__ ae2,
                       float* __restrict__ we) {
    int j = blockIdx.x * 256 + threadIdx.x;
    if (j < N) {
        float s = 0.f, c = 0.f;
        for (int b2 = 0; b2 < 32; b2++) { s += cs[b2 * N + j]; c += cc[b2 * N + j]; }
        mean[j] = c > 0.f ? s / c : 0.f;
    }
    if (blockIdx.x == 8) {
        int t = threadIdx.x;
        if (t < 4) {
            float s = 0.f;
            for (int c = 0; c < 64; c++) s += We1[t * 64 + c] * ae1[t * 64 + c];
            we[t] = s;
        } else if (t == 4) {
            float s = 0.f;
            for (int c = 0; c < 64; c++) s += We2[c] * ae2[c];
            we[4] = s;
        }
    }
}

// ---------------- feature GEMM + attention-dot epilogue + tf32 output ----------------
template<int TM>
__global__ void __launch_bounds__(256) k_gemm(const float* __restrict__ A,
        const float* __restrict__ B, float* __restrict__ Ct, int K, int ldb, int ldn,
        const float* __restrict__ asrc, const float* __restrict__ adst,
        float* __restrict__ oas, float* __restrict__ oad) {
    constexpr int R = TM / 16;
    __shared__ float As2[16][TM + 1];
    __shared__ float Bs2[16][64];
    int h = blockIdx.y;
    int m0 = blockIdx.x * TM, n0 = h * 64;
    int tid = threadIdx.x;
    int tx = tid & 15, ty = tid >> 4;
    float acc[R][4];
#pragma unroll
    for (int r = 0; r < R; r++)
#pragma unroll
        for (int c = 0; c < 4; c++) acc[r][c] = 0.f;
    for (int k0 = 0; k0 < K; k0 += 16) {
#pragma unroll
        for (int l = 0; l < R; l++) {
            int e = l * 256 + tid;
            As2[e & 15][e >> 4] = A[(size_t)(m0 + (e >> 4)) * K + k0 + (e & 15)];
        }
#pragma unroll
        for (int l = 0; l < 4; l++) {
            int e = l * 256 + tid;
            Bs2[e >> 6][e & 63] = B[(size_t)(k0 + (e >> 6)) * ldb + n0 + (e & 63)];
        }
        __syncthreads();
#pragma unroll
        for (int kk = 0; kk < 16; kk++) {
            float a[R], bb[4];
#pragma unroll
            for (int r = 0; r < R; r++) a[r] = As2[kk][ty * R + r];
#pragma unroll
            for (int c = 0; c < 4; c++) bb[c] = Bs2[kk][tx * 4 + c];
#pragma unroll
            for (int r = 0; r < R; r++)
#pragma unroll
                for (int c = 0; c < 4; c++) acc[r][c] += a[r] * bb[c];
        }
        __syncthreads();
    }
    int lane = tid & 31;
    float asv[4], adv[4];
#pragma unroll
    for (int c = 0; c < 4; c++) {
        asv[c] = asrc[h * 64 + tx * 4 + c];
        adv[c] = adst[h * 64 + tx * 4 + c];
    }
#pragma unroll
    for (int r = 0; r < R; r++) {
        int row = m0 + ty * R + r;
        float ds = 0.f, dd = 0.f;
#pragma unroll
        for (int c = 0; c < 4; c++) {
            float v = acc[r][c];
            Ct[(size_t)row * ldn + n0 + tx * 4 + c] = to_tf32(v);
            ds += v * asv[c];
            dd += v * adv[c];
        }
#pragma unroll
        for (int m = 1; m < 16; m <<= 1) {
            ds += __shfl_xor_sync(0xffffffffu, ds, m);
            dd += __shfl_xor_sync(0xffffffffu, dd, m);
        }
        if ((lane & 15) == 0) { oas[h * N + row] = ds; oad[h * N + row] = dd; }
    }
}

// ---------------- fused logits + softmax + tf32 MMA (flash-style, split-K) ----------------
template<int H, int S>
__global__ void __launch_bounds__(256) k_fattn(const float* __restrict__ edge,
        const float* __restrict__ mean, const float* __restrict__ as_,
        const float* __restrict__ ad_, const float* __restrict__ wep, int woff,
        const float* __restrict__ Bf, float* __restrict__ part, float* __restrict__ rsum) {
    constexpr int KR = N / S;
    constexpr int CH = KR / KCH;
    const int ldn = H * 64;
    __shared__ float As[64][33];
    __shared__ float Bs[KCH][68];
    __shared__ float s_as[KR];
    __shared__ float rred[256];
    int tid = threadIdx.x;
    int m0 = blockIdx.x * 64, h = blockIdx.y, s = blockIdx.z;
    int kb = s * KR;
    for (int idx = tid; idx < KR; idx += 256) s_as[idx] = as_[h * N + kb + idx];
    int j = tid & 63, ig = tid >> 6;
    float adj = ad_[h * N + m0 + j];
    float me  = mean[m0 + j];
    float wev = wep[woff + h];
    int brow = tid >> 3, bc8 = tid & 7;
    int wid = tid >> 5, lane = tid & 31;
    int wm = wid >> 2, wn = wid & 3, gid = lane >> 2, tig = lane & 3;
    float acc[2][2][4];
#pragma unroll
    for (int mt = 0; mt < 2; mt++)
#pragma unroll
        for (int nt = 0; nt < 2; nt++)
#pragma unroll
            for (int q = 0; q < 4; q++) acc[mt][nt][q] = 0.f;
    float racc = 0.f;
    float ev[8];
    float4 bv0, bv1;
#pragma unroll
    for (int b = 0; b < 8; b++)
        ev[b] = edge[(size_t)(kb + ig + 4 * b) * N + m0 + j];
    bv0 = *(const float4*)(Bf + (size_t)(kb + brow) * ldn + h * 64 + bc8 * 8);
    bv1 = *(const float4*)(Bf + (size_t)(kb + brow) * ldn + h * 64 + bc8 * 8 + 4);
    __syncthreads();   // s_as ready

    for (int c = 0; c < CH; c++) {
        int kc = kb + c * KCH;
#pragma unroll
        for (int b = 0; b < 8; b++) {
            int il = ig + 4 * b;
            int i_g = kc + il;
            bool diag = (i_g == m0 + j);
            float e = diag ? me : ev[b];
            bool on = diag || (ev[b] > 0.f);
            float v = s_as[c * KCH + il] + adj + e * wev;
            v = fmaxf(v, 0.2f * v);
            float p = on ? to_tf32(__expf(v)) : 0.f;
            As[j][il] = p;
            racc += p;
        }
        *(float4*)&Bs[brow][bc8 * 8]     = bv0;
        *(float4*)&Bs[brow][bc8 * 8 + 4] = bv1;
        __syncthreads();
        if (c + 1 < CH) {
            int kn = kc + KCH;
#pragma unroll
            for (int b = 0; b < 8; b++)
                ev[b] = edge[(size_t)(kn + ig + 4 * b) * N + m0 + j];
            bv0 = *(const float4*)(Bf + (size_t)(kn + brow) * ldn + h * 64 + bc8 * 8);
            bv1 = *(const float4*)(Bf + (size_t)(kn + brow) * ldn + h * 64 + bc8 * 8 + 4);
        }
#pragma unroll
        for (int kk = 0; kk < 4; kk++) {
            float a[2][4], bq[2][2];
#pragma unroll
            for (int mt = 0; mt < 2; mt++) {
                int r0 = wm * 32 + mt * 16 + gid;
                a[mt][0] = As[r0][kk * 8 + tig];
                a[mt][1] = As[r0 + 8][kk * 8 + tig];
                a[mt][2] = As[r0][kk * 8 + tig + 4];
                a[mt][3] = As[r0 + 8][kk * 8 + tig + 4];
            }
#pragma unroll
            for (int nt = 0; nt < 2; nt++) {
                int c0 = wn * 16 + nt * 8 + gid;
                bq[nt][0] = Bs[kk * 8 + tig][c0];
                bq[nt][1] = Bs[kk * 8 + tig + 4][c0];
            }
#pragma unroll
            for (int mt = 0; mt < 2; mt++)
#pragma unroll
                for (int nt = 0; nt < 2; nt++)
                    asm volatile("mma.sync.aligned.m16n8k8.row.col.f32.tf32.tf32.f32 "
                                 "{%0,%1,%2,%3}, {%4,%5,%6,%7}, {%8,%9}, {%0,%1,%2,%3};"
                                 : "+f"(acc[mt][nt][0]), "+f"(acc[mt][nt][1]),
                                   "+f"(acc[mt][nt][2]), "+f"(acc[mt][nt][3])
                                 : "r"(__float_as_uint(a[mt][0])), "r"(__float_as_uint(a[mt][1])),
                                   "r"(__float_as_uint(a[mt][2])), "r"(__float_as_uint(a[mt][3])),
                                   "r"(__float_as_uint(bq[nt][0])), "r"(__float_as_uint(bq[nt][1])));
        }
        __syncthreads();
    }

    rred[tid] = racc;
    __syncthreads();
    if (tid < 64) {
        float ssum = rred[tid] + rred[64 + tid] + rred[128 + tid] + rred[192 + tid];
        rsum[((size_t)s * H + h) * N + m0 + tid] = ssum;
    }
#pragma unroll
    for (int mt = 0; mt < 2; mt++)
#pragma unroll
        for (int nt = 0; nt < 2; nt++) {
            int c0 = wn * 16 + nt * 8 + tig * 2;
#pragma unroll
            for (int pr = 0; pr < 2; pr++) {
                int r = m0 + wm * 32 + mt * 16 + gid + pr * 8;
                part[((size_t)s * N + r) * ldn + h * 64 + c0]     = acc[mt][nt][2 * pr + 0];
                part[((size_t)s * N + r) * ldn + h * 64 + c0 + 1] = acc[mt][nt][2 * pr + 1];
            }
        }
}

// ---------------- combine splits: normalize + bias + ELU ----------------
template<int S, int HH>
__global__ void k_comb(const float* __restrict__ part, const float* __restrict__ rsum,
                       const float* __restrict__ bias, float* __restrict__ out) {
    const int ldn = HH * 64;
    int idx = blockIdx.x * 256 + threadIdx.x;
    if (idx >= N * ldn) return;
    int n = idx / ldn, hc = idx % ldn, h = hc >> 6;
    float cs = 0.f, rs = 0.f;
#pragma unroll
    for (int s = 0; s < S; s++) {
        cs += part[((size_t)s * N + n) * ldn + hc];
        rs += rsum[((size_t)s * HH + h) * N + n];
    }
    float v = cs / rs + bias[hc];
    out[idx] = v > 0.f ? v : (expf(v) - 1.f);
}

// ---------------- segment-mean pool + final linear ----------------
__global__ void k_pool(const float* __restrict__ o2, const int* __restrict__ batch,
                       const float* __restrict__ Wl, const float* __restrict__ bl,
                       float* __restrict__ out) {
    int g = blockIdx.x;
    __shared__ float acc[4][64];
    __shared__ float cnts[4];
    int tid = threadIdx.x, q = tid >> 6, c = tid & 63;
    float s = 0.f, cn = 0.f;
    for (int n = q; n < N; n += 4) {
        if (batch[n] == g) { s += o2[(size_t)n * 64 + c]; cn += 1.f; }
    }
    acc[q][c] = s;
    if (c == 0) cnts[q] = cn;
    __syncthreads();
    if (q == 0) {
        float tot = acc[0][c] + acc[1][c] + acc[2][c] + acc[3][c];
        float cc = cnts[0] + cnts[1] + cnts[2] + cnts[3];
        acc[0][c] = tot / fmaxf(cc, 1.f);
    }
    __syncthreads();
    if (tid < OUTF) {
        float s2 = bl[tid];
        for (int c2 = 0; c2 < 64; c2++) s2 += acc[0][c2] * Wl[c2 * OUTF + tid];
        out[g * OUTF + tid] = s2;
    }
}

// ---------------- host ----------------
extern "C" void kernel_launch(void* const* d_in, const int* in_sizes, int n_in,
                              void* d_out, int out_size) {
    const float* x        = (const float*)d_in[0];
    const float* attn     = (const float*)d_in[1];
    const int*   batch    = (const int*)d_in[2];
    const float* w_agg    = (const float*)d_in[3];
    const float* b_agg    = (const float*)d_in[4];
    const float* W1       = (const float*)d_in[5];
    const float* att_src1 = (const float*)d_in[6];
    const float* att_dst1 = (const float*)d_in[7];
    const float* We1      = (const float*)d_in[8];
    const float* att_e1   = (const float*)d_in[9];
    const float* bias1    = (const float*)d_in[10];
    const float* W2       = (const float*)d_in[11];
    const float* att_src2 = (const float*)d_in[12];
    const float* att_dst2 = (const float*)d_in[13];
    const float* We2      = (const float*)d_in[14];
    const float* att_e2   = (const float*)d_in[15];
    const float* bias2    = (const float*)d_in[16];
    const float* W_lin    = (const float*)d_in[17];
    const float* b_lin    = (const float*)d_in[18];

    float* out  = (float*)d_out;
    float* edge = out + (out_size - NN);

    float *csum, *ccnt, *meanp, *wep, *hf1t, *hf2t, *asp, *adp, *partp, *rsump, *o1p, *o2p;
    cudaGetSymbolAddress((void**)&csum,  g_csum);
    cudaGetSymbolAddress((void**)&ccnt,  g_ccnt);
    cudaGetSymbolAddress((void**)&meanp, g_mean);
    cudaGetSymbolAddress((void**)&wep,   g_we);
    cudaGetSymbolAddress((void**)&hf1t,  g_hf1t);
    cudaGetSymbolAddress((void**)&hf2t,  g_hf2t);
    cudaGetSymbolAddress((void**)&asp,   g_as);
    cudaGetSymbolAddress((void**)&adp,   g_ad);
    cudaGetSymbolAddress((void**)&partp, g_part);
    cudaGetSymbolAddress((void**)&rsump, g_rsum);
    cudaGetSymbolAddress((void**)&o1p,   g_o1);
    cudaGetSymbolAddress((void**)&o2p,   g_o2);

    // edge + column stats (fused)
    k_aggT<<<dim3(32, 32), 256>>>(attn, w_agg, b_agg, edge, csum, ccnt);
    // features layer1 + attention dots (independent of aggT)
    k_gemm<64><<<dim3(32, 4), 256>>>(x, W1, hf1t, 128, 256, 256,
                                     att_src1, att_dst1, asp, adp);
    // means + edge-weight scalars
    k_mean<<<9, 256>>>(csum, ccnt, meanp, We1, att_e1, We2, att_e2, wep);

    // ---- GAT layer 1 (H=4, S=2) ----
    k_fattn<4, 2><<<dim3(32, 4, 2), 256>>>(edge, meanp, asp, adp, wep, 0, hf1t, partp, rsump);
    k_comb<2, 4><<<N * 256 / 256, 256>>>(partp, rsump, bias1, o1p);

    // ---- GAT layer 2 (H=1, S=8) ----
    k_gemm<32><<<dim3(64, 1), 256>>>(o1p, W2, hf2t, 256, 64, 64,
                                     att_src2, att_dst2, asp, adp);
    k_fattn<1, 8><<<dim3(32, 1, 8), 256>>>(edge, meanp, asp, adp, wep, 4, hf2t, partp, rsump);
    k_comb<8, 1><<<N * 64 / 256, 256>>>(partp, rsump, bias2, o2p);

    // ---- pool + final linear ----
    k_pool<<<NG, 256>>>(o2p, batch, W_lin, b_lin, out);
}